// round 13
// baseline (speedup 1.0000x reference)
#include <cuda_runtime.h>
#include <math.h>

#define MM 48
#define LL 48
#define NN 256
#define NT 128            // threads per CTA (= per sample)
#define KPJ 12            // k's per thread (4-aligned contiguous segment)
#define STR2 64           // float2 row stride for ab (16B-aligned)
#define SLOTS (NT * KPJ)  // 1536 checkpoint slots
#define CPB 12            // checkpoint rows: cp[b] = SUF(4b+3)

// smem floats: ab float2[48*64] (=6144 f) | cp[12*1536] | u[48] | prt[40]
#define SM_AB  0
#define SM_CP  (2 * LL * STR2)
#define SM_U   (SM_CP + CPB * SLOTS)
#define SM_PRT (SM_U + LL)
#define SMEMF  (SM_PRT + 40)

typedef unsigned long long u64;

// Blackwell packed f32x2 (each lane = IEEE f32 mul/fma; ptxas won't auto-emit)
__device__ __forceinline__ float2 f2mul(float2 a, float2 b) {
    u64 ra = *reinterpret_cast<u64*>(&a);
    u64 rb = *reinterpret_cast<u64*>(&b);
    u64 rc;
    asm("mul.rn.f32x2 %0,%1,%2;" : "=l"(rc) : "l"(ra), "l"(rb));
    return *reinterpret_cast<float2*>(&rc);
}
__device__ __forceinline__ float2 f2fma(float2 a, float2 b, float2 c) {
    u64 ra = *reinterpret_cast<u64*>(&a);
    u64 rb = *reinterpret_cast<u64*>(&b);
    u64 rc = *reinterpret_cast<u64*>(&c);
    u64 rd;
    asm("fma.rn.f32x2 %0,%1,%2,%3;" : "=l"(rd) : "l"(ra), "l"(rb), "l"(rc));
    return *reinterpret_cast<float2*>(&rd);
}

// Accurate f32 sincos: Cody-Waite FMA range reduction + Taylor polys.
// |x| < ~80, ~1-2 ulp, immune to --use_fast_math (no libm).
__device__ __forceinline__ void sincos_acc(float x, float* s, float* c) {
    float kf = rintf(x * 0.63661977236758134f);
    int k = (int)kf;
    float r = fmaf(kf, -1.57079637050628662109375f, x);
    r = fmaf(kf, 4.37113882867379290e-8f, r);
    float r2 = r * r;
    float ps = fmaf(r2, 2.7557314297e-06f, -1.9841270114e-04f);
    ps = fmaf(r2, ps, 8.3333337680e-03f);
    ps = fmaf(r2, ps, -1.6666667163e-01f);
    float sr = fmaf(r * r2, ps, r);
    float pc = fmaf(r2, -2.7557314297e-07f, 2.4760126951e-05f);
    pc = fmaf(r2, pc, -1.3888889225e-03f);
    pc = fmaf(r2, pc, 4.1666667908e-02f);
    float cr = fmaf(r2 * r2, pc, fmaf(r2, -0.5f, 1.0f));
    switch (k & 3) {
        case 0: *s = sr;  *c = cr;  break;
        case 1: *s = cr;  *c = -sr; break;
        case 2: *s = -sr; *c = -cr; break;
        default:*s = -cr; *c = sr;  break;
    }
}

// 12 float2 <-> regs (6x LDS.128); 12 floats <-> regs (3x LDS/STS.128)
__device__ __forceinline__ void ld12f2(const float2* p, float2* v) {
    const float4* q = reinterpret_cast<const float4*>(p);
#pragma unroll
    for (int i = 0; i < 6; i++) {
        float4 t = q[i];
        v[2 * i]     = make_float2(t.x, t.y);
        v[2 * i + 1] = make_float2(t.z, t.w);
    }
}
__device__ __forceinline__ void ld12(const float* p, float* v) {
    const float4* q = reinterpret_cast<const float4*>(p);
    float4 x = q[0], y = q[1], z = q[2];
    v[0] = x.x; v[1] = x.y; v[2]  = x.z; v[3]  = x.w;
    v[4] = y.x; v[5] = y.y; v[6]  = y.z; v[7]  = y.w;
    v[8] = z.x; v[9] = z.y; v[10] = z.z; v[11] = z.w;
}
__device__ __forceinline__ void st12(float* p, const float* v) {
    float4* q = reinterpret_cast<float4*>(p);
    q[0] = make_float4(v[0], v[1], v[2],  v[3]);
    q[1] = make_float4(v[4], v[5], v[6],  v[7]);
    q[2] = make_float4(v[8], v[9], v[10], v[11]);
}

__global__ __launch_bounds__(NT, 2) void fused_kernel(
    const float* __restrict__ inp,      // (N,L)
    const float* __restrict__ theta,    // (L,M)
    const float* __restrict__ coef,     // (M,)
    const float* __restrict__ rand_u,   // (L,N)
    float* __restrict__ out)            // N*L bits then N probs
{
    extern __shared__ float sm[];
    float2* ab  = reinterpret_cast<float2*>(sm + SM_AB);  // [l*STR2 + k]
    float*  cp  = sm + SM_CP;
    float*  ush = sm + SM_U;
    float*  prt = sm + SM_PRT;

    const int n = blockIdx.x, tid = threadIdx.x;
    const int lane = tid & 31, wid = tid >> 5;

    // ---- Phase A: AoS embedding tile (f32 rounding matches reference) ----
    const float PI2F = 1.57079637050628662109375f;
#pragma unroll
    for (int e = tid; e < LL * STR2; e += NT) {
        int l = e / STR2, c = e - l * STR2;
        float a = 0.f, b = 0.f;
        if (c < MM) {
            float ang = inp[n * LL + l] * ((float)(c + 1) * PI2F);
            float sv, cv; sincos_acc(ang, &sv, &cv);
            float st, ct; sincos_acc(theta[l * MM + c], &st, &ct);
            float cf = coef[c];
            a = cf * (ct * cv - st * sv);
            b = cf * (st * cv + ct * sv);
        }
        ab[e] = make_float2(a, b);
    }
    if (tid < LL) ush[tid] = rand_u[tid * NN + n];
    __syncthreads();

    // ---- segment decode: thread owns m and k in [kst, kst+11], kst % 4 == 0 ----
    int m = 47, kst = 48;                 // default: idle thread (reads zero pad)
    {
        int t = tid;
        for (int mm = 0; mm < MM; mm++) {
            int s = mm & ~3;
            int nseg = (MM - s + KPJ - 1) / KPJ;
            if (t < nseg) { m = mm; kst = s + t * KPJ; break; }
            t -= nseg;
        }
    }

    // ---- Phase B: backward scan; checkpoint SUF (weight baked) at l%4==3 ----
    {
        float run[KPJ];
#pragma unroll
        for (int j = 0; j < KPJ; j++) {
            int k = kst + j;
            run[j] = (k < m || k >= MM) ? 0.f : ((k == m) ? 1.f : 2.f);
        }
        for (int l = LL - 1; l >= 0; l--) {
            if ((l & 3) == 3)
                st12(cp + (l >> 2) * SLOTS + tid * KPJ, run);
            float2 mv = ab[l * STR2 + m];
            float2 kv[KPJ];
            ld12f2(ab + l * STR2 + kst, kv);
#pragma unroll
            for (int j = 0; j < KPJ; j++)
                run[j] *= fmaf(mv.x, kv[j].x, mv.y * kv[j].y);
        }
    }
    // cp rows written and read by the same thread — no barrier needed.

    float P[KPJ];
#pragma unroll
    for (int j = 0; j < KPJ; j++)
        P[j] = (kst + j < m || kst + j >= MM) ? 0.f : 1.f;

    // suffix registers: r3 = SUF(4b+3) = cp[b]; r1 = SUF(4b+1) = r3*d(4b+3)*d(4b+2)
    float r1[KPJ], r3[KPJ];
    auto rebuild = [&](int b) {
        ld12(cp + b * SLOTS + tid * KPJ, r3);
        float2 kv[KPJ];
        int l = 4 * b + 3;
        float2 mv = ab[l * STR2 + m];
        ld12f2(ab + l * STR2 + kst, kv);
#pragma unroll
        for (int j = 0; j < KPJ; j++)
            r1[j] = r3[j] * fmaf(mv.x, kv[j].x, mv.y * kv[j].y);
        l = 4 * b + 2;
        mv = ab[l * STR2 + m];
        ld12f2(ab + l * STR2 + kst, kv);
#pragma unroll
        for (int j = 0; j < KPJ; j++)
            r1[j] *= fmaf(mv.x, kv[j].x, mv.y * kv[j].y);
    };
    rebuild(0);

    float denom0 = 1.f;
    int Kexp = 0;
    u64 bits = 0ull;

    // ---- Phase C: 24 two-site rounds; packed f32x2 speculative accumulation ----
    // qA = (T00,T01)-terms, qB = (T10,T11)-terms;  S_b(l0) = T_{b,0}+T_{b,1}.
    auto round2 = [&](int l0, const float* suf, int bnext) {
        float uv1 = ush[l0], uv2 = ush[l0 + 1];
        float2 abm1 = ab[l0 * STR2 + m];
        float2 abm2 = ab[(l0 + 1) * STR2 + m];
        float2 k1[KPJ], k2[KPJ];
        ld12f2(ab + l0 * STR2 + kst, k1);
        ld12f2(ab + (l0 + 1) * STR2 + kst, k2);

        float2 qA[KPJ], qB[KPJ];
        float2 tA = make_float2(0.f, 0.f), tB = make_float2(0.f, 0.f);
        float2 tA2 = make_float2(0.f, 0.f), tB2 = make_float2(0.f, 0.f);
#pragma unroll
        for (int j = 0; j < KPJ; j++) {
            float2 cc1 = f2mul(abm1, k1[j]);                    // (aa1, bb1)
            float2 cc2 = f2mul(abm2, k2[j]);                    // (aa2, bb2)
            float2 pab = f2mul(make_float2(P[j], P[j]), cc1);   // (pa, pb)
            qA[j] = f2mul(make_float2(pab.x, pab.x), cc2);      // (q00, q01)
            qB[j] = f2mul(make_float2(pab.y, pab.y), cc2);      // (q10, q11)
            float2 sfp = make_float2(suf[j], suf[j]);
            if (j & 1) { tA2 = f2fma(qA[j], sfp, tA2); tB2 = f2fma(qB[j], sfp, tB2); }
            else       { tA  = f2fma(qA[j], sfp, tA);  tB  = f2fma(qB[j], sfp, tB); }
        }
        float t00 = tA.x + tA2.x, t01 = tA.y + tA2.y;
        float t10 = tB.x + tB2.x, t11 = tB.y + tB2.y;
#pragma unroll
        for (int o = 16; o; o >>= 1) {
            t00 += __shfl_xor_sync(0xffffffffu, t00, o);
            t01 += __shfl_xor_sync(0xffffffffu, t01, o);
            t10 += __shfl_xor_sync(0xffffffffu, t10, o);
            t11 += __shfl_xor_sync(0xffffffffu, t11, o);
        }
        const int par = ((l0 >> 1) & 1) * 16;
        if (lane == 0) {
            prt[par + wid]      = t00;
            prt[par + 4 + wid]  = t01;
            prt[par + 8 + wid]  = t10;
            prt[par + 12 + wid] = t11;
        }
        if (bnext >= 0) rebuild(bnext);    // fills bar wait, bit-independent
        __syncthreads();

        // redundant decisions (identical on all threads)
        const float4* q = reinterpret_cast<const float4*>(prt + par);
        float4 v;
        v = q[0]; float T00 = (v.x + v.y) + (v.z + v.w);
        v = q[1]; float T01 = (v.x + v.y) + (v.z + v.w);
        v = q[2]; float T10 = (v.x + v.y) + (v.z + v.w);
        v = q[3]; float T11 = (v.x + v.y) + (v.z + v.w);

        float S1  = T10 + T11;
        float den1 = fabsf((T00 + T01) + S1);
        int b1 = (uv1 * den1 < fabsf(S1)) ? 1 : 0;
        if (l0 == 0) denom0 = den1;
        float S0p = b1 ? T10 : T00;
        float S1p = b1 ? T11 : T01;
        float den2 = fabsf(S0p + S1p);
        int b2 = (uv2 * den2 < fabsf(S1p)) ? 1 : 0;
        int eb = (__float_as_int(den2) >> 23) & 0xFF;   // exact 2^-k renorm
        int kk = eb ? (eb - 127) >> 1 : 0;
        Kexp += kk;
        float scale = __int_as_float((127 - kk) << 23);
        bits |= ((u64)b1 << l0) | ((u64)b2 << (l0 + 1));
#pragma unroll
        for (int j = 0; j < KPJ; j++) {                 // select + scale only
            float2 qs = b1 ? qB[j] : qA[j];
            P[j] = (b2 ? qs.y : qs.x) * scale;
        }
    };

#pragma unroll 1
    for (int b = 0; b < CPB; b++) {
        round2(4 * b,     r1, -1);
        round2(4 * b + 2, r3, (b + 1 < CPB) ? b + 1 : -1);
    }

    // ---- epilogue: final inner = sum w*P (true value * 2^Kexp), outputs ----
    float sf = 0.f;
#pragma unroll
    for (int j = 0; j < KPJ; j++) {
        int k = kst + j;
        float w = (k < m || k >= MM) ? 0.f : ((k == m) ? 1.f : 2.f);
        sf += w * P[j];
    }
#pragma unroll
    for (int o = 16; o; o >>= 1) sf += __shfl_xor_sync(0xffffffffu, sf, o);
    if (lane == 0) prt[32 + wid] = sf;
    __syncthreads();

    if (tid < LL) out[n * LL + tid] = (float)((bits >> tid) & 1ull);
    if (tid == 0) {
        double Sf = (double)((prt[32] + prt[33]) + (prt[34] + prt[35]));
        double pmv = ldexp(fabs(Sf), Kexp) / (double)denom0;
        out[NN * LL + n] = (float)pmv;
    }
}

extern "C" void kernel_launch(void* const* d_in, const int* in_sizes, int n_in,
                              void* d_out, int out_size) {
    const float* inp    = (const float*)d_in[0];   // (N,L)
    const float* theta  = (const float*)d_in[1];   // (L,M)
    const float* coef   = (const float*)d_in[2];   // (M,)
    const float* rand_u = (const float*)d_in[3];   // (L,N)
    float* out = (float*)d_out;

    static int smem_set = 0;
    if (!smem_set) {
        cudaFuncSetAttribute(fused_kernel,
                             cudaFuncAttributeMaxDynamicSharedMemorySize,
                             SMEMF * (int)sizeof(float));
        smem_set = 1;
    }
    fused_kernel<<<NN, NT, SMEMF * sizeof(float)>>>(inp, theta, coef, rand_u, out);
}